// round 5
// baseline (speedup 1.0000x reference)
#include <cuda_runtime.h>
#include <cuda_bf16.h>
#include <cstdint>
#include <cstddef>

// Problem constants
#define BATCH 512
#define TSTEPS 256
#define HID 512
#define G4 2048
#define DEC_STEPS 42

// Persistent-kernel config
#define NCTA 128
#define TM 128                 // batch rows per CTA
#define TNR 64                 // reordered gate cols per CTA (16 logical x 4 gates)
#define KC 64                  // k per chunk
#define NKC 8                  // 512/64
#define PITCHB 144             // bytes per smem row (72 bf16: 64 data + 8 pad)
#define BTILE (64 * PITCHB)            // 9216  (per dtype per chunk)
#define BCHUNK (2 * BTILE)             // 18432 (hi+lo)
#define BTOT (NKC * BCHUNK)            // 147456
#define ATILE (TM * PITCHB)            // 18432 (per dtype)
#define ASTAGE (2 * ATILE)             // 36864 (hi+lo)
#define AOFF BTOT
#define SMEM_TOTAL (BTOT + 2 * ASTAGE) // 221184

// ------------------------- device scratch (no allocs) ----------------------
__device__ __align__(128) __nv_bfloat16 g_whi[G4 * HID];
__device__ __align__(128) __nv_bfloat16 g_wlo[G4 * HID];
__device__ __align__(128) __nv_bfloat16 g_hhi0[BATCH * HID];
__device__ __align__(128) __nv_bfloat16 g_hlo0[BATCH * HID];
__device__ __align__(128) __nv_bfloat16 g_hhi1[BATCH * HID];
__device__ __align__(128) __nv_bfloat16 g_hlo1[BATCH * HID];
__device__ float g_hf[BATCH * HID];
__device__ float g_c [BATCH * HID];
__device__ float g_G0[BATCH * G4];
__device__ float g_br[G4];
__device__ float g_wihr[G4];
__device__ volatile unsigned g_flags[NCTA];

// ------------------------------ helpers ------------------------------------
__device__ __forceinline__ uint32_t smem_u32(const void* p) {
    uint32_t a;
    asm("{ .reg .u64 t; cvta.to.shared.u64 t, %1; cvt.u32.u64 %0, t; }" : "=r"(a) : "l"(p));
    return a;
}
__device__ __forceinline__ void cpasync16(uint32_t s, const void* g) {
    asm volatile("cp.async.cg.shared.global [%0], [%1], 16;" :: "r"(s), "l"(g));
}
__device__ __forceinline__ void cpasync_commit() {
    asm volatile("cp.async.commit_group;" ::: "memory");
}
template <int N> __device__ __forceinline__ void cpasync_wait() {
    asm volatile("cp.async.wait_group %0;" :: "n"(N) : "memory");
}
__device__ __forceinline__ void ldsm_x4(uint32_t* r, uint32_t addr) {
    asm volatile("ldmatrix.sync.aligned.m8n8.x4.shared.b16 {%0,%1,%2,%3}, [%4];"
                 : "=r"(r[0]), "=r"(r[1]), "=r"(r[2]), "=r"(r[3]) : "r"(addr));
}
__device__ __forceinline__ void mma16816(float* c, const uint32_t* a, uint32_t b0, uint32_t b1) {
    asm volatile(
        "mma.sync.aligned.m16n8k16.row.col.f32.bf16.bf16.f32 "
        "{%0,%1,%2,%3}, {%4,%5,%6,%7}, {%8,%9}, {%0,%1,%2,%3};"
        : "+f"(c[0]), "+f"(c[1]), "+f"(c[2]), "+f"(c[3])
        : "r"(a[0]), "r"(a[1]), "r"(a[2]), "r"(a[3]), "r"(b0), "r"(b1));
}
__device__ __forceinline__ float sigm(float v) { return 1.0f / (1.0f + expf(-v)); }

// -------------------------- init / prep kernels -----------------------------
__global__ void init_state(uint32_t* hhi, uint32_t* hlo) {
    int i = blockIdx.x * 256 + threadIdx.x;
    if (i < BATCH * HID / 2) { hhi[i] = 0u; hlo[i] = 0u; }
    if (i < NCTA) g_flags[i] = 0u;
}

// Split W_hh into bf16 hi/lo with gate-interleaved row reorder:
//   old row r = q*512 + jn*16 + s  ->  new row = jn*64 + q*16 + s
__global__ void wprep(const float* __restrict__ Whh,
                      const float* __restrict__ b_ih, const float* __restrict__ b_hh,
                      const float* __restrict__ Wih,
                      __nv_bfloat16* __restrict__ whi, __nv_bfloat16* __restrict__ wlo,
                      float* __restrict__ br, float* __restrict__ wihr)
{
    int i = blockIdx.x * 256 + threadIdx.x;
    if (i >= G4 * HID) return;
    int old_r = i / HID;
    int k = i - old_r * HID;
    int q = old_r >> 9;
    int rem = old_r & 511;
    int jn = rem >> 4;
    int s = rem & 15;
    int new_r = jn * 64 + q * 16 + s;
    float w = Whh[i];
    __nv_bfloat16 hi = __float2bfloat16(w);
    whi[new_r * HID + k] = hi;
    wlo[new_r * HID + k] = __float2bfloat16(w - __bfloat162float(hi));
    if (k == 0) {
        br[new_r] = b_ih[old_r] + b_hh[old_r];
        wihr[new_r] = Wih[old_r];
    }
}

// ----------------------- persistent encoder kernel --------------------------
// grid (32, 4) = 128 CTAs, 512 threads. CTA tile 128(m) x 64(n-reordered).
// B slice resident in smem; A (h hi/lo) streamed per step; c in registers.
// Runs t = 0..255 (LSTM steps) and t = 256 (G0 = h@W^T + bias) with a
// hand-rolled inter-CTA barrier between steps.
__global__ __launch_bounds__(512, 1)
void lstm_persistent(const __nv_bfloat16* __restrict__ whi_g,
                     const __nv_bfloat16* __restrict__ wlo_g,
                     const float* __restrict__ br, const float* __restrict__ wihr,
                     const float* __restrict__ x,
                     __nv_bfloat16* __restrict__ hhi0, __nv_bfloat16* __restrict__ hlo0,
                     __nv_bfloat16* __restrict__ hhi1, __nv_bfloat16* __restrict__ hlo1,
                     float* __restrict__ hf, float* __restrict__ cg,
                     float* __restrict__ G0)
{
    extern __shared__ __align__(16) char smem[];
    const uint32_t sb = smem_u32(smem);
    const int tid = threadIdx.x;
    const int wid = tid >> 5;
    const int l = tid & 31;
    const int wm = wid >> 2;              // 0..3 (32 rows each)
    const int wn = wid & 3;               // 0..3 (= gate q, 16 cols)
    const int jn = blockIdx.x;            // 0..31
    const int m0 = blockIdx.y * TM;
    const int n0 = jn * TNR;
    const int bid = blockIdx.y * 32 + jn; // 0..127

    // ---- load resident B (W hi/lo slice) : 8 chunks x 2 dtypes ----
#pragma unroll
    for (int it = 0; it < 16; ++it) {
        int slot = tid + it * 512;        // 0..8191
        int seg = slot & 7;
        int r = (slot >> 3) & 63;
        int dt = (slot >> 9) & 1;
        int kc = slot >> 10;
        const __nv_bfloat16* src = dt ? wlo_g : whi_g;
        cpasync16(sb + (uint32_t)(kc * BCHUNK + dt * BTILE + r * PITCHB + seg * 16),
                  (const char*)src + ((size_t)(n0 + r) * HID + kc * KC) * 2 + seg * 16);
    }
    cpasync_commit();
    cpasync_wait<0>();
    __syncthreads();

    // ldmatrix per-lane offsets
    const uint32_t aoff = (uint32_t)((l & 15) * PITCHB + (l >> 4) * 16);
    const uint32_t boff = (uint32_t)(((l & 7) + ((l >> 4) << 3)) * PITCHB + ((l >> 3) & 1) * 16);

    // epilogue mapping: thread -> (row, 4 consecutive s-cols); c in registers
    const int erow = tid >> 2;            // 0..127
    const int es0 = (tid & 3) * 4;        // s base (0,4,8,12)
    const int grow = m0 + erow;
    float creg[4] = {0.f, 0.f, 0.f, 0.f};
    float* sg = reinterpret_cast<float*>(smem + AOFF);   // reuses A staging

    auto loadA = [&](int stage, int kc, const __nv_bfloat16* ah, const __nv_bfloat16* al) {
        uint32_t dst = sb + AOFF + (uint32_t)(stage * ASTAGE);
#pragma unroll
        for (int it = 0; it < 2; ++it) {
            int slot = tid + it * 512;    // 0..1023
            int seg = slot & 7;
            int r = slot >> 3;
            size_t gofs = ((size_t)(m0 + r) * HID + kc * KC) * 2 + seg * 16;
            cpasync16(dst + (uint32_t)(r * PITCHB + seg * 16), (const char*)ah + gofs);
            cpasync16(dst + ATILE + (uint32_t)(r * PITCHB + seg * 16), (const char*)al + gofs);
        }
        cpasync_commit();
    };

#pragma unroll 1
    for (int t = 0; t <= TSTEPS; ++t) {
        const __nv_bfloat16* ah = (t & 1) ? hhi1 : hhi0;
        const __nv_bfloat16* al = (t & 1) ? hlo1 : hlo0;
        __nv_bfloat16* oh = (t & 1) ? hhi0 : hhi1;
        __nv_bfloat16* ol = (t & 1) ? hlo0 : hlo1;

        float acc[2][2][4];
#pragma unroll
        for (int mt = 0; mt < 2; ++mt)
#pragma unroll
            for (int nt = 0; nt < 2; ++nt)
#pragma unroll
                for (int v = 0; v < 4; ++v) acc[mt][nt][v] = 0.0f;

        loadA(0, 0, ah, al);
        loadA(1, 1, ah, al);

#pragma unroll 1
        for (int kc = 0; kc < NKC; ++kc) {
            if (kc < NKC - 1) cpasync_wait<1>(); else cpasync_wait<0>();
            __syncthreads();

            const uint32_t stA = sb + AOFF + (uint32_t)((kc & 1) * ASTAGE + wm * 32 * PITCHB);
            const uint32_t stB = sb + (uint32_t)(kc * BCHUNK + wn * 16 * PITCHB);
#pragma unroll
            for (int ks = 0; ks < 4; ++ks) {
                const uint32_t ka = (uint32_t)(ks * 32);   // 16 bf16 = 32B
                uint32_t ahr[2][4], alr[2][4], bhr[4], blr[4];
#pragma unroll
                for (int mt = 0; mt < 2; ++mt) {
                    ldsm_x4(ahr[mt], stA + (uint32_t)(mt * 16 * PITCHB) + ka + aoff);
                    ldsm_x4(alr[mt], stA + ATILE + (uint32_t)(mt * 16 * PITCHB) + ka + aoff);
                }
                ldsm_x4(bhr, stB + ka + boff);
                ldsm_x4(blr, stB + BTILE + ka + boff);
#pragma unroll
                for (int mt = 0; mt < 2; ++mt)
#pragma unroll
                    for (int nt = 0; nt < 2; ++nt) {
                        mma16816(acc[mt][nt], ahr[mt], bhr[nt * 2], bhr[nt * 2 + 1]);
                        mma16816(acc[mt][nt], ahr[mt], blr[nt * 2], blr[nt * 2 + 1]);
                        mma16816(acc[mt][nt], alr[mt], bhr[nt * 2], bhr[nt * 2 + 1]);
                    }
            }
            __syncthreads();                 // all warps done with stage kc&1
            if (kc + 2 < NKC) loadA(kc & 1, kc + 2, ah, al);
        }

        // ---- epilogue: acc -> smem [128][68] (cols = q*16+s) ----
#pragma unroll
        for (int mt = 0; mt < 2; ++mt)
#pragma unroll
            for (int nt = 0; nt < 2; ++nt) {
                int r0 = wm * 32 + mt * 16 + (l >> 2);
                int cb = wn * 16 + nt * 8 + (l & 3) * 2;
                *reinterpret_cast<float2*>(&sg[r0 * 68 + cb]) =
                    make_float2(acc[mt][nt][0], acc[mt][nt][1]);
                *reinterpret_cast<float2*>(&sg[(r0 + 8) * 68 + cb]) =
                    make_float2(acc[mt][nt][2], acc[mt][nt][3]);
            }
        __syncthreads();

        if (t < TSTEPS) {
            const float xv = x[grow * TSTEPS + t];
            __align__(8) __nv_bfloat16 h4[4], l4[4];
#pragma unroll
            for (int i = 0; i < 4; ++i) {
                int s = es0 + i;
                float gi = sg[erow * 68 +  0 + s] + br[n0 +  0 + s] + xv * wihr[n0 +  0 + s];
                float gf = sg[erow * 68 + 16 + s] + br[n0 + 16 + s] + xv * wihr[n0 + 16 + s];
                float gg = sg[erow * 68 + 32 + s] + br[n0 + 32 + s] + xv * wihr[n0 + 32 + s];
                float go = sg[erow * 68 + 48 + s] + br[n0 + 48 + s] + xv * wihr[n0 + 48 + s];
                float cn = sigm(gf) * creg[i] + sigm(gi) * tanhf(gg);
                creg[i] = cn;
                float hv = sigm(go) * tanhf(cn);
                h4[i] = __float2bfloat16(hv);
                l4[i] = __float2bfloat16(hv - __bfloat162float(h4[i]));
                if (t == TSTEPS - 1) {
                    hf[grow * HID + jn * 16 + s] = hv;
                    cg[grow * HID + jn * 16 + s] = cn;
                }
            }
            int hidx = grow * HID + jn * 16 + es0;
            *reinterpret_cast<uint2*>(&oh[hidx]) = *reinterpret_cast<uint2*>(h4);
            *reinterpret_cast<uint2*>(&ol[hidx]) = *reinterpret_cast<uint2*>(l4);
        } else {
            // G0 mode: gates + bias only (original gate-major layout)
            size_t base = (size_t)grow * G4;
#pragma unroll
            for (int i = 0; i < 4; ++i) {
                int s = es0 + i;
#pragma unroll
                for (int q = 0; q < 4; ++q)
                    G0[base + q * HID + jn * 16 + s] =
                        sg[erow * 68 + q * 16 + s] + br[n0 + q * 16 + s];
            }
        }

        // ---- inter-CTA barrier (skip after final G0 step) ----
        if (t < TSTEPS) {
            __threadfence();
            __syncthreads();
            if (tid == 0) g_flags[bid] = (unsigned)(t + 1);
            if (tid < NCTA) {
                while (g_flags[tid] < (unsigned)(t + 1)) { }
            }
            __threadfence();
            __syncthreads();
        }
    }
}

// ------------------------------- decoder ------------------------------------
__global__ __launch_bounds__(256)
void decode_kernel(const float* __restrict__ hidden,
                   const float* __restrict__ cell,
                   const float* __restrict__ G0,
                   const float* __restrict__ Wih,
                   const float* __restrict__ Wout,
                   const float* __restrict__ bout,
                   float* __restrict__ out)
{
    const int b = blockIdx.x;
    const int t = threadIdx.x;

    __shared__ float sh[HID];
    __shared__ float red[9];

    float g0[2][4], wv[2][4], cc[2], wo[2];
#pragma unroll
    for (int s = 0; s < 2; ++s) {
        int jj = t + s * 256;
#pragma unroll
        for (int q = 0; q < 4; ++q) {
            g0[s][q] = G0[b * G4 + q * HID + jj];
            wv[s][q] = Wih[q * HID + jj];
        }
        cc[s] = cell[b * HID + jj];
        wo[s] = Wout[jj];
        sh[jj] = hidden[b * HID + jj];
    }
    const float bo = bout[0];
    __syncthreads();

    for (int step = 0; step < DEC_STEPS; ++step) {
        float p = sh[t] * wo[0] + sh[t + 256] * wo[1];
#pragma unroll
        for (int o = 16; o > 0; o >>= 1)
            p += __shfl_down_sync(0xffffffffu, p, o);
        if ((t & 31) == 0) red[t >> 5] = p;
        __syncthreads();
        if (t < 8) {
            float v = red[t];
            v += __shfl_down_sync(0x000000ffu, v, 4);
            v += __shfl_down_sync(0x000000ffu, v, 2);
            v += __shfl_down_sync(0x000000ffu, v, 1);
            if (t == 0) red[8] = v + bo;
        }
        __syncthreads();
        const float ov = red[8];
        if (t == 0) out[b * DEC_STEPS + step] = ov;

        float hn[2];
#pragma unroll
        for (int s = 0; s < 2; ++s) {
            float gi = g0[s][0] + ov * wv[s][0];
            float gf = g0[s][1] + ov * wv[s][1];
            float gg = g0[s][2] + ov * wv[s][2];
            float go = g0[s][3] + ov * wv[s][3];
            float cn = sigm(gf) * cc[s] + sigm(gi) * tanhf(gg);
            hn[s] = sigm(go) * tanhf(cn);
        }
        __syncthreads();
        sh[t]       = hn[0];
        sh[t + 256] = hn[1];
        __syncthreads();
    }
}

// ------------------------------- launch -------------------------------------
extern "C" void kernel_launch(void* const* d_in, const int* in_sizes, int n_in,
                              void* d_out, int out_size)
{
    const float* x     = (const float*)d_in[0];
    const float* W_ih  = (const float*)d_in[1];
    const float* W_hh  = (const float*)d_in[2];
    const float* b_ih  = (const float*)d_in[3];
    const float* b_hh  = (const float*)d_in[4];
    const float* W_out = (const float*)d_in[5];
    const float* b_out = (const float*)d_in[6];
    float* out = (float*)d_out;

    __nv_bfloat16 *whi, *wlo, *hhi0, *hlo0, *hhi1, *hlo1;
    float *hf, *c, *G0, *br, *wihr;
    cudaGetSymbolAddress((void**)&whi,  g_whi);
    cudaGetSymbolAddress((void**)&wlo,  g_wlo);
    cudaGetSymbolAddress((void**)&hhi0, g_hhi0);
    cudaGetSymbolAddress((void**)&hlo0, g_hlo0);
    cudaGetSymbolAddress((void**)&hhi1, g_hhi1);
    cudaGetSymbolAddress((void**)&hlo1, g_hlo1);
    cudaGetSymbolAddress((void**)&hf,   g_hf);
    cudaGetSymbolAddress((void**)&c,    g_c);
    cudaGetSymbolAddress((void**)&G0,   g_G0);
    cudaGetSymbolAddress((void**)&br,   g_br);
    cudaGetSymbolAddress((void**)&wihr, g_wihr);

    cudaFuncSetAttribute(lstm_persistent, cudaFuncAttributeMaxDynamicSharedMemorySize, SMEM_TOTAL);

    init_state<<<(BATCH * HID / 2 + 255) / 256, 256>>>((uint32_t*)hhi0, (uint32_t*)hlo0);
    wprep<<<(G4 * HID + 255) / 256, 256>>>(W_hh, b_ih, b_hh, W_ih, whi, wlo, br, wihr);

    dim3 grid(32, 4);          // 128 CTAs, 1 per SM (smem-forced), all resident
    lstm_persistent<<<grid, 512, SMEM_TOTAL>>>(whi, wlo, br, wihr, x,
                                               hhi0, hlo0, hhi1, hlo1,
                                               hf, c, G0);

    decode_kernel<<<BATCH, 256>>>(hf, c, G0, W_ih, W_out, b_out, out);
}

// round 6
// speedup vs baseline: 2.3468x; 2.3468x over previous
#include <cuda_runtime.h>
#include <cuda_fp16.h>
#include <cuda_bf16.h>
#include <cstdint>
#include <cstddef>

// Problem constants
#define BATCH 512
#define TSTEPS 256
#define HID 512
#define G4 2048
#define DEC_STEPS 42

// MMA step config: CTA 64(m) x 128(n-reordered), 512 threads (16 warps 4x4),
// warp tile 16(m) x 32(n). KC=64, 8 chunks, 3-stage cp.async pipeline.
#define TM 64
#define TNR 128
#define KC 64
#define NKC 8
#define NSTAGE 3
#define PITCH 144                         // bytes per smem row (72 fp16)
#define ATILE (TM * PITCH)                // 9216
#define BTILE (TNR * PITCH)               // 18432
#define STAGE (ATILE + BTILE)             // 27648
#define SMEM_TOTAL (NSTAGE * STAGE)       // 82944

// ------------------------- device scratch (no allocs) ----------------------
__device__ __align__(128) __half g_wh[G4 * HID];      // fp16 reordered W_hh
__device__ __align__(128) __half g_h0[BATCH * HID];   // fp16 h ping
__device__ __align__(128) __half g_h1[BATCH * HID];   // fp16 h pong
__device__ float g_hf[BATCH * HID];
__device__ float g_c [BATCH * HID];
__device__ float g_G0[BATCH * G4];
__device__ float g_br[G4];
__device__ float g_wihr[G4];

// ------------------------------ helpers ------------------------------------
__device__ __forceinline__ uint32_t smem_u32(const void* p) {
    uint32_t a;
    asm("{ .reg .u64 t; cvta.to.shared.u64 t, %1; cvt.u32.u64 %0, t; }" : "=r"(a) : "l"(p));
    return a;
}
__device__ __forceinline__ void cpasync16(uint32_t s, const void* g) {
    asm volatile("cp.async.cg.shared.global [%0], [%1], 16;" :: "r"(s), "l"(g));
}
__device__ __forceinline__ void cpasync_commit() {
    asm volatile("cp.async.commit_group;" ::: "memory");
}
template <int N> __device__ __forceinline__ void cpasync_wait() {
    asm volatile("cp.async.wait_group %0;" :: "n"(N) : "memory");
}
__device__ __forceinline__ void ldsm_x4(uint32_t* r, uint32_t addr) {
    asm volatile("ldmatrix.sync.aligned.m8n8.x4.shared.b16 {%0,%1,%2,%3}, [%4];"
                 : "=r"(r[0]), "=r"(r[1]), "=r"(r[2]), "=r"(r[3]) : "r"(addr));
}
__device__ __forceinline__ void mma16816(float* c, const uint32_t* a, uint32_t b0, uint32_t b1) {
    asm volatile(
        "mma.sync.aligned.m16n8k16.row.col.f32.f16.f16.f32 "
        "{%0,%1,%2,%3}, {%4,%5,%6,%7}, {%8,%9}, {%0,%1,%2,%3};"
        : "+f"(c[0]), "+f"(c[1]), "+f"(c[2]), "+f"(c[3])
        : "r"(a[0]), "r"(a[1]), "r"(a[2]), "r"(a[3]), "r"(b0), "r"(b1));
}
__device__ __forceinline__ float sigm(float v) { return 1.0f / (1.0f + expf(-v)); }

// -------------------------- init / prep kernels -----------------------------
__global__ void init_state(uint32_t* h0, float* c) {
    int i = blockIdx.x * 256 + threadIdx.x;
    if (i < BATCH * HID / 2) h0[i] = 0u;
    if (i < BATCH * HID) c[i] = 0.0f;
}

// Convert W_hh to fp16 with gate-interleaved row reorder:
//   old row r = q*512 + jn*32 + s  ->  new row = jn*128 + q*32 + s
__global__ void wprep(const float* __restrict__ Whh,
                      const float* __restrict__ b_ih, const float* __restrict__ b_hh,
                      const float* __restrict__ Wih,
                      __half* __restrict__ wh,
                      float* __restrict__ br, float* __restrict__ wihr)
{
    int i = blockIdx.x * 256 + threadIdx.x;
    if (i >= G4 * HID) return;
    int old_r = i / HID;
    int k = i - old_r * HID;
    int q = old_r >> 9;
    int rem = old_r & 511;
    int jn = rem >> 5;
    int s = rem & 31;
    int new_r = jn * 128 + q * 32 + s;
    wh[new_r * HID + k] = __float2half(Whh[i]);
    if (k == 0) {
        br[new_r] = b_ih[old_r] + b_hh[old_r];
        wihr[new_r] = Wih[old_r];
    }
}

// ----------------------------- tensor LSTM step -----------------------------
__global__ __launch_bounds__(512, 1)
void lstm_mma_step(const __half* __restrict__ hin,
                   const __half* __restrict__ wh,
                   const float* __restrict__ br, const float* __restrict__ wihr,
                   const float* __restrict__ x, int t,
                   float* __restrict__ c,
                   __half* __restrict__ hout,
                   float* __restrict__ hf,     // non-null: also store fp32 h
                   float* __restrict__ G0)     // non-null: G0 mode (gates+bias only)
{
    extern __shared__ __align__(16) char smem[];
    const uint32_t sb = smem_u32(smem);
    const int tid = threadIdx.x;
    const int wid = tid >> 5;
    const int l = tid & 31;
    const int wm = wid & 3;               // 0..3: 16-row m tile
    const int wn = wid >> 2;              // 0..3: 32-col n tile (= gate q)
    const int jn = blockIdx.x;            // 0..15
    const int m0 = blockIdx.y * TM;
    const int n0 = jn * TNR;              // reordered W row base

    // --------------- cp.async tile loaders ----------------------------------
    auto load_chunk = [&](int stage, int kc) {
        uint32_t st = sb + stage * STAGE;
        int k0 = kc * KC;
        {   // A: 64 rows x 8 segs = 512 transfers
            int r = tid >> 3, seg = tid & 7;
            cpasync16(st + (uint32_t)(r * PITCH + seg * 16),
                      (const char*)hin + ((size_t)(m0 + r) * HID + k0) * 2 + seg * 16);
        }
#pragma unroll
        for (int it = 0; it < 2; ++it) {   // B: 128 rows x 8 segs = 1024
            int slot = tid + it * 512;
            int r = slot >> 3, seg = slot & 7;
            cpasync16(st + ATILE + (uint32_t)(r * PITCH + seg * 16),
                      (const char*)wh + ((size_t)(n0 + r) * HID + k0) * 2 + seg * 16);
        }
        cpasync_commit();
    };

    // per-lane ldmatrix byte offsets
    const uint32_t aoff = (uint32_t)((l & 15) * PITCH + (l >> 4) * 16);
    const uint32_t boff = (uint32_t)(((l & 7) + ((l >> 4) << 3)) * PITCH + ((l >> 3) & 1) * 16);

    float acc[4][4];
#pragma unroll
    for (int nt = 0; nt < 4; ++nt)
#pragma unroll
        for (int v = 0; v < 4; ++v) acc[nt][v] = 0.0f;

    load_chunk(0, 0);
    load_chunk(1, 1);

#pragma unroll 1
    for (int kc = 0; kc < NKC; ++kc) {
        if (kc < NKC - 1) cpasync_wait<1>(); else cpasync_wait<0>();
        __syncthreads();
        if (kc + 2 < NKC) load_chunk((kc + 2) % NSTAGE, kc + 2);

        const uint32_t st = sb + (kc % NSTAGE) * STAGE;
        const uint32_t stA = st + (uint32_t)(wm * 16 * PITCH);
        const uint32_t stB = st + ATILE + (uint32_t)(wn * 32 * PITCH);
#pragma unroll
        for (int ks = 0; ks < 4; ++ks) {
            const uint32_t ka = (uint32_t)(ks * 32);   // 16 fp16 = 32B
            uint32_t ar[4], b0r[4], b1r[4];
            ldsm_x4(ar, stA + ka + aoff);
            ldsm_x4(b0r, stB + ka + boff);
            ldsm_x4(b1r, stB + (uint32_t)(16 * PITCH) + ka + boff);
            mma16816(acc[0], ar, b0r[0], b0r[1]);
            mma16816(acc[1], ar, b0r[2], b0r[3]);
            mma16816(acc[2], ar, b1r[0], b1r[1]);
            mma16816(acc[3], ar, b1r[2], b1r[3]);
        }
    }
    __syncthreads();

    // ------------------------------- epilogue --------------------------------
    // acc -> smem [64][132] fp32 (cols = q*32+s)
    float* sg = reinterpret_cast<float*>(smem);
#pragma unroll
    for (int nt = 0; nt < 4; ++nt) {
        int r0 = wm * 16 + (l >> 2);
        int cb = wn * 32 + nt * 8 + (l & 3) * 2;
        *reinterpret_cast<float2*>(&sg[r0 * 132 + cb]) = make_float2(acc[nt][0], acc[nt][1]);
        *reinterpret_cast<float2*>(&sg[(r0 + 8) * 132 + cb]) = make_float2(acc[nt][2], acc[nt][3]);
    }
    __syncthreads();

    const int srow = tid >> 3;            // 64 rows, 8 threads/row
    const int row = m0 + srow;
    const int s0 = (tid & 7) * 4;
    const float xv = (G0 == nullptr) ? x[row * TSTEPS + t] : 0.0f;

    if (G0 != nullptr) {
        size_t base = (size_t)row * G4;
#pragma unroll
        for (int i = 0; i < 4; ++i) {
            int s = s0 + i;
#pragma unroll
            for (int q = 0; q < 4; ++q)
                G0[base + q * HID + jn * 32 + s] =
                    sg[srow * 132 + q * 32 + s] + br[n0 + q * 32 + s];
        }
    } else {
        __align__(8) __half h4[4];
#pragma unroll
        for (int i = 0; i < 4; ++i) {
            int s = s0 + i;
            float gi = sg[srow * 132 +  0 + s] + br[n0 +   0 + s] + xv * wihr[n0 +   0 + s];
            float gf = sg[srow * 132 + 32 + s] + br[n0 +  32 + s] + xv * wihr[n0 +  32 + s];
            float gg = sg[srow * 132 + 64 + s] + br[n0 +  64 + s] + xv * wihr[n0 +  64 + s];
            float go = sg[srow * 132 + 96 + s] + br[n0 +  96 + s] + xv * wihr[n0 +  96 + s];
            int idx = row * HID + jn * 32 + s;
            float cn = sigm(gf) * c[idx] + sigm(gi) * tanhf(gg);
            c[idx] = cn;
            float hv = sigm(go) * tanhf(cn);
            h4[i] = __float2half(hv);
            if (hf != nullptr) hf[idx] = hv;
        }
        *reinterpret_cast<uint2*>(&hout[row * HID + jn * 32 + s0]) =
            *reinterpret_cast<uint2*>(h4);
    }
}

// ------------------------------- decoder ------------------------------------
__global__ __launch_bounds__(256)
void decode_kernel(const float* __restrict__ hidden,
                   const float* __restrict__ cell,
                   const float* __restrict__ G0,
                   const float* __restrict__ Wih,
                   const float* __restrict__ Wout,
                   const float* __restrict__ bout,
                   float* __restrict__ out)
{
    const int b = blockIdx.x;
    const int t = threadIdx.x;

    __shared__ float sh[HID];
    __shared__ float red[9];

    float g0[2][4], wv[2][4], cc[2], wo[2];
#pragma unroll
    for (int s = 0; s < 2; ++s) {
        int jj = t + s * 256;
#pragma unroll
        for (int q = 0; q < 4; ++q) {
            g0[s][q] = G0[b * G4 + q * HID + jj];
            wv[s][q] = Wih[q * HID + jj];
        }
        cc[s] = cell[b * HID + jj];
        wo[s] = Wout[jj];
        sh[jj] = hidden[b * HID + jj];
    }
    const float bo = bout[0];
    __syncthreads();

    for (int step = 0; step < DEC_STEPS; ++step) {
        float p = sh[t] * wo[0] + sh[t + 256] * wo[1];
#pragma unroll
        for (int o = 16; o > 0; o >>= 1)
            p += __shfl_down_sync(0xffffffffu, p, o);
        if ((t & 31) == 0) red[t >> 5] = p;
        __syncthreads();
        if (t < 8) {
            float v = red[t];
            v += __shfl_down_sync(0x000000ffu, v, 4);
            v += __shfl_down_sync(0x000000ffu, v, 2);
            v += __shfl_down_sync(0x000000ffu, v, 1);
            if (t == 0) red[8] = v + bo;
        }
        __syncthreads();
        const float ov = red[8];
        if (t == 0) out[b * DEC_STEPS + step] = ov;

        float hn[2];
#pragma unroll
        for (int s = 0; s < 2; ++s) {
            float gi = g0[s][0] + ov * wv[s][0];
            float gf = g0[s][1] + ov * wv[s][1];
            float gg = g0[s][2] + ov * wv[s][2];
            float go = g0[s][3] + ov * wv[s][3];
            float cn = sigm(gf) * cc[s] + sigm(gi) * tanhf(gg);
            hn[s] = sigm(go) * tanhf(cn);
        }
        __syncthreads();
        sh[t]       = hn[0];
        sh[t + 256] = hn[1];
        __syncthreads();
    }
}

// ------------------------------- launch -------------------------------------
extern "C" void kernel_launch(void* const* d_in, const int* in_sizes, int n_in,
                              void* d_out, int out_size)
{
    const float* x     = (const float*)d_in[0];
    const float* W_ih  = (const float*)d_in[1];
    const float* W_hh  = (const float*)d_in[2];
    const float* b_ih  = (const float*)d_in[3];
    const float* b_hh  = (const float*)d_in[4];
    const float* W_out = (const float*)d_in[5];
    const float* b_out = (const float*)d_in[6];
    float* out = (float*)d_out;

    __half *wh, *h0, *h1;
    float *hf, *c, *G0, *br, *wihr;
    cudaGetSymbolAddress((void**)&wh, g_wh);
    cudaGetSymbolAddress((void**)&h0, g_h0);
    cudaGetSymbolAddress((void**)&h1, g_h1);
    cudaGetSymbolAddress((void**)&hf, g_hf);
    cudaGetSymbolAddress((void**)&c,  g_c);
    cudaGetSymbolAddress((void**)&G0, g_G0);
    cudaGetSymbolAddress((void**)&br, g_br);
    cudaGetSymbolAddress((void**)&wihr, g_wihr);

    cudaFuncSetAttribute(lstm_mma_step, cudaFuncAttributeMaxDynamicSharedMemorySize, SMEM_TOTAL);

    init_state<<<(BATCH * HID + 255) / 256, 256>>>((uint32_t*)h0, c);
    wprep<<<(G4 * HID + 255) / 256, 256>>>(W_hh, b_ih, b_hh, W_ih, wh, br, wihr);

    dim3 grid(G4 / TNR, BATCH / TM);     // (16, 8) = 128 CTAs
    dim3 block(512);

    for (int t = 0; t < TSTEPS; ++t) {
        const __half* hin = (t & 1) ? h1 : h0;
        __half* hout      = (t & 1) ? h0 : h1;
        float* hfp = (t == TSTEPS - 1) ? hf : nullptr;
        lstm_mma_step<<<grid, block, SMEM_TOTAL>>>(hin, wh, br, wihr, x, t,
                                                   c, hout, hfp, nullptr);
    }
    // T=256 even: final hidden in h0 (fp16) / hf (fp32), cell in c

    lstm_mma_step<<<grid, block, SMEM_TOTAL>>>(h0, wh, br, wihr, x, 0,
                                               c, h1, nullptr, G0);

    decode_kernel<<<BATCH, 256>>>(hf, c, G0, W_ih, W_out, b_out, out);
}